// round 13
// baseline (speedup 1.0000x reference)
#include <cuda_runtime.h>
#include <cuda_fp16.h>
#include <math.h>

// Problem constants
#define BB 16
#define SS 512
#define DM 256
#define HH 8
#define DKV 32
#define CTXW 288   // DV*(H+1)
#define EPS 1e-5f

// -------- scratch (device globals; no allocation allowed) --------
__device__ float  g_Q[BB * SS * DM];
__device__ float  g_K[BB * SS * DM];
__device__ float  g_V[BB * SS * DM];
__device__ __half g_attn[(long)BB * HH * SS * SS];            // 67 MB (fp16)
__device__ unsigned g_maskp[(long)BB * HH * SS * SS / 32];    // 4.2 MB bit-packed mask
__device__ float  g_vp2[BB * SS * DKV];
__device__ float  g_ctx[BB * SS * CTXW];
__device__ float  g_fc[BB * SS * DM];

// -------- one-time stream/event setup (load-time ctor: every
// kernel_launch call performs IDENTICAL work; no in-call guards) --------
static cudaStream_t g_s1;
static cudaEvent_t  g_evFork, g_evPack, g_evAttn, g_evCtx2, g_evGate;
namespace {
struct StreamInit {
    StreamInit() {
        cudaStreamCreateWithFlags(&g_s1, cudaStreamNonBlocking);
        cudaEventCreateWithFlags(&g_evFork, cudaEventDisableTiming);
        cudaEventCreateWithFlags(&g_evPack, cudaEventDisableTiming);
        cudaEventCreateWithFlags(&g_evAttn, cudaEventDisableTiming);
        cudaEventCreateWithFlags(&g_evCtx2, cudaEventDisableTiming);
        cudaEventCreateWithFlags(&g_evGate, cudaEventDisableTiming);
    }
};
StreamInit g_stream_init_;
}

// ---- packed f32x2 FMA (Blackwell FFMA2; PTX-only, ptxas won't auto-fuse) ----
__device__ __forceinline__ void ffma2(float2 &d, const float2 &a, const float2 &b) {
    unsigned long long &dd = reinterpret_cast<unsigned long long &>(d);
    const unsigned long long &aa = reinterpret_cast<const unsigned long long &>(a);
    const unsigned long long &bb = reinterpret_cast<const unsigned long long &>(b);
    asm("fma.rn.f32x2 %0, %1, %2, %0;" : "+l"(dd) : "l"(aa), "l"(bb));
}

// ---- cp.async helpers (8-byte: keeps conflict-free stride-17 smem layout) ----
__device__ __forceinline__ void cp_async8(void* smem, const void* gmem) {
    unsigned saddr = (unsigned)__cvta_generic_to_shared(smem);
    asm volatile("cp.async.ca.shared.global [%0], [%1], 8;" :: "r"(saddr), "l"(gmem));
}
__device__ __forceinline__ void cp_commit() {
    asm volatile("cp.async.commit_group;" ::: "memory");
}
template<int N>
__device__ __forceinline__ void cp_wait() {
    asm volatile("cp.async.wait_group %0;" :: "n"(N) : "memory");
}

// dynamic smem size for attn5: Sb[32][528] f32 + KV2[2][64][17] float2
#define ATTN_SMEM (32 * 528 * 4 + 2 * 64 * 17 * 8)

// ============================================================
// Mask bit-pack: 134 MB int32 -> 4.2 MB bits. Warp ballot, one STG
// per 32 ints. Runs on side stream overlapped with QKV GEMM.
// ============================================================
#define MASK_WORDS ((long)BB * HH * SS * SS / 32)
__global__ __launch_bounds__(256) void maskpack_kernel(
    const int* __restrict__ mask, unsigned* __restrict__ mp)
{
    const int lane = threadIdx.x & 31;
    const int gw = blockIdx.x * 8 + (threadIdx.x >> 5);
    const int nw = gridDim.x * 8;
    for (long w = gw; w < MASK_WORDS; w += nw) {
        int v = mask[w * 32 + lane];
        unsigned bits = __ballot_sync(0xffffffffu, v != 0);
        if (lane == 0) mp[w] = bits;
    }
}

// ============================================================
// SGEMM v2 (single-buffered inner loop), z-dispatched over up to
// 3 independent (A,B,C) triples. tile 128x64, BK=16, 256 threads.
// ============================================================
__global__ __launch_bounds__(256) void sgemm2_kernel(
    const float* __restrict__ A0, const float* __restrict__ A1, const float* __restrict__ A2,
    const float* __restrict__ B0, const float* __restrict__ B1, const float* __restrict__ B2,
    float* __restrict__ C0, float* __restrict__ C1, float* __restrict__ C2,
    int K, int lda, int ldb, int ldc)
{
    const int z = blockIdx.z;
    const float* A = (z == 0) ? A0 : (z == 1) ? A1 : A2;
    const float* B = (z == 0) ? B0 : (z == 1) ? B1 : B2;
    float*       C = (z == 0) ? C0 : (z == 1) ? C1 : C2;

    __shared__ __align__(16) float As[16][130];  // [k][m], m contiguous
    __shared__ __align__(16) float Bs[16][68];   // [k][n]
    const int tid = threadIdx.x;
    const int tx = tid & 15, ty = tid >> 4;
    const int m0 = blockIdx.y * 128, n0 = blockIdx.x * 64;

    float2 acc[4][4];
#pragma unroll
    for (int i = 0; i < 4; i++)
#pragma unroll
        for (int j = 0; j < 4; j++) acc[i][j] = make_float2(0.f, 0.f);

    for (int k0 = 0; k0 < K; k0 += 16) {
#pragma unroll
        for (int t = 0; t < 2; t++) {
            int idx = tid + t * 256;
            int row = idx >> 2, kq = idx & 3;
            float4 v = *(const float4*)&A[(size_t)(m0 + row) * lda + k0 + kq * 4];
            As[kq * 4 + 0][row] = v.x; As[kq * 4 + 1][row] = v.y;
            As[kq * 4 + 2][row] = v.z; As[kq * 4 + 3][row] = v.w;
        }
        {
            int kk = tid >> 4, nq = tid & 15;
            *(float4*)&Bs[kk][nq * 4] =
                *(const float4*)&B[(size_t)(k0 + kk) * ldb + n0 + nq * 4];
        }
        __syncthreads();
#pragma unroll
        for (int kk = 0; kk < 16; kk++) {
            float2 a[4];
#pragma unroll
            for (int i = 0; i < 4; i++) a[i] = *(float2*)&As[kk][ty * 8 + 2 * i];
            float2 bA = *(float2*)&Bs[kk][tx * 4];
            float2 bB = *(float2*)&Bs[kk][tx * 4 + 2];
            float2 bj[4] = {{bA.x, bA.x}, {bA.y, bA.y}, {bB.x, bB.x}, {bB.y, bB.y}};
#pragma unroll
            for (int j = 0; j < 4; j++)
#pragma unroll
                for (int i = 0; i < 4; i++) ffma2(acc[i][j], a[i], bj[j]);
        }
        __syncthreads();
    }
#pragma unroll
    for (int i = 0; i < 4; i++) {
        int m = m0 + ty * 8 + 2 * i;
        float4 lo = {acc[i][0].x, acc[i][1].x, acc[i][2].x, acc[i][3].x};
        float4 hi = {acc[i][0].y, acc[i][1].y, acc[i][2].y, acc[i][3].y};
        *(float4*)&C[(size_t)m * ldc + n0 + tx * 4] = lo;
        *(float4*)&C[(size_t)(m + 1) * ldc + n0 + tx * 4] = hi;
    }
}

// ============================================================
// SGEMM narrow: N=32 (vp2 projection). tile 128x32, BK=16.
// ============================================================
__global__ __launch_bounds__(256) void sgemm_n32_kernel(
    const float* __restrict__ A, const float* __restrict__ B, float* __restrict__ C,
    int K, int lda)
{
    __shared__ __align__(16) float As[16][130];
    __shared__ __align__(16) float Bs[16][36];
    const int tid = threadIdx.x;
    const int tx = tid & 7, ty = tid >> 3;
    const int m0 = blockIdx.y * 128;

    float2 acc[2][4];
#pragma unroll
    for (int i = 0; i < 2; i++)
#pragma unroll
        for (int j = 0; j < 4; j++) acc[i][j] = make_float2(0.f, 0.f);

    for (int k0 = 0; k0 < K; k0 += 16) {
#pragma unroll
        for (int t = 0; t < 2; t++) {
            int idx = tid + t * 256;
            int row = idx >> 2, kq = idx & 3;
            float4 v = *(const float4*)&A[(size_t)(m0 + row) * lda + k0 + kq * 4];
            As[kq * 4 + 0][row] = v.x; As[kq * 4 + 1][row] = v.y;
            As[kq * 4 + 2][row] = v.z; As[kq * 4 + 3][row] = v.w;
        }
        if (tid < 128) {
            int kk = tid >> 3, nq = tid & 7;
            *(float4*)&Bs[kk][nq * 4] =
                *(const float4*)&B[(size_t)(k0 + kk) * DKV + nq * 4];
        }
        __syncthreads();
#pragma unroll
        for (int kk = 0; kk < 16; kk++) {
            float2 a0 = *(float2*)&As[kk][ty * 4];
            float2 a1 = *(float2*)&As[kk][ty * 4 + 2];
            float2 bA = *(float2*)&Bs[kk][tx * 4];
            float2 bB = *(float2*)&Bs[kk][tx * 4 + 2];
            float2 bj[4] = {{bA.x, bA.x}, {bA.y, bA.y}, {bB.x, bB.x}, {bB.y, bB.y}};
#pragma unroll
            for (int j = 0; j < 4; j++) { ffma2(acc[0][j], a0, bj[j]); ffma2(acc[1][j], a1, bj[j]); }
        }
        __syncthreads();
    }
#pragma unroll
    for (int i = 0; i < 2; i++) {
        int m = m0 + ty * 4 + 2 * i;
        float4 lo = {acc[i][0].x, acc[i][1].x, acc[i][2].x, acc[i][3].x};
        float4 hi = {acc[i][0].y, acc[i][1].y, acc[i][2].y, acc[i][3].y};
        *(float4*)&C[(size_t)m * DKV + tx * 4] = lo;
        *(float4*)&C[(size_t)(m + 1) * DKV + tx * 4] = hi;
    }
}

// ============================================================
// Fused attention v6 (R12): bit-packed mask (one 8B broadcast load
// per row per chunk replaces 4 scattered LDG), 32-q tile, 2 q/thread,
// cp.async double-buffered K/V, fp16 attn store.
// grid (S/32, H, B), 256 threads.
// ============================================================
__global__ __launch_bounds__(256, 2) void attn6_kernel(
    const float* __restrict__ Q, const float* __restrict__ K, const float* __restrict__ V,
    const unsigned* __restrict__ maskp, __half* __restrict__ attn, float* __restrict__ ctx)
{
    extern __shared__ __align__(16) char smem_raw[];
    float  (*Sb)[528]      = reinterpret_cast<float (*)[528]>(smem_raw);             // [32][528]
    float2 (*KV2)[64][17]  = reinterpret_cast<float2 (*)[64][17]>(smem_raw + 32 * 528 * 4); // [2][64][17]

    const int q0 = blockIdx.x * 32;
    const int h = blockIdx.y;
    const int b = blockIdx.z;
    const int tid = threadIdx.x;
    const int lane = tid & 31, warp = tid >> 5;

    const float* Qb = &Q[((size_t)(b * SS + q0)) * DM + h * DKV];
    const float* Kb = &K[((size_t)(b * SS)) * DM + h * DKV];
    const float* Vb = &V[((size_t)(b * SS)) * DM + h * DKV];
    const long long mrow0 = (((long long)(b * HH + h)) * SS + q0) * SS;

    const int lkk = tid >> 4, ldp = tid & 15;   // cp.async loader mapping

    // ---- issue K chunk 0 -> buf 0 immediately ----
#pragma unroll
    for (int t = 0; t < 4; t++)
        cp_async8(&KV2[0][lkk + t * 16][ldp], Kb + (size_t)(lkk + t * 16) * DM + ldp * 2);
    cp_commit();

    // ---- stage scaled Q (32x16 float2) into KV2[1], then to registers ----
    {
        int sq = tid >> 3, dq = tid & 7;
#pragma unroll
        for (int t = 0; t < 2; t++) {
            int dp = dq + t * 8;
            float2 v = *(const float2*)&Qb[(size_t)sq * DM + dp * 2];
            v.x *= 0.17677669529663687f; v.y *= 0.17677669529663687f;
            KV2[1][sq][dp] = v;
        }
    }
    __syncthreads();
    const int p  = (warp << 1) | (lane >> 4);   // 0..15 row-pair id
    const int qA = p, qB = p + 16;
    float2 qrA[16], qrB[16];
#pragma unroll
    for (int dp = 0; dp < 16; dp++) { qrA[dp] = KV2[1][qA][dp]; qrB[dp] = KV2[1][qB][dp]; }
    __syncthreads();   // all Q reads done before it=0 prefetch overwrites buf 1

    // ---- scores + mask bits (2 q-rows per thread) ----
    const int kb = lane & 15;
    // word base for each row; (mrow + k0) is a multiple of 64 -> uint2 aligned
    const unsigned* mpA = maskp + ((mrow0 + (long long)qA * SS) >> 5);
    const unsigned* mpB = maskp + ((mrow0 + (long long)qB * SS) >> 5);
    for (int it = 0; it < 8; it++) {
        const int cur = it & 1;
        const int k0 = it * 64;
        if (it < 7) {
            const float* src = Kb + (size_t)(k0 + 64) * DM;
#pragma unroll
            for (int t = 0; t < 4; t++)
                cp_async8(&KV2[cur ^ 1][lkk + t * 16][ldp], src + (size_t)(lkk + t * 16) * DM + ldp * 2);
            cp_commit();
        }
        // broadcast 8B mask-bit loads (same word across each half-warp)
        uint2 mwA = *(const uint2*)(mpA + (k0 >> 5));
        uint2 mwB = *(const uint2*)(mpB + (k0 >> 5));
        if (it < 7) cp_wait<1>(); else cp_wait<0>();
        __syncthreads();
#pragma unroll
        for (int jj = 0; jj < 4; jj++) {
            int kk = kb + jj * 16;
            // jj 0,1 -> word .x ; jj 2,3 -> word .y ; bit kb + (jj&1)*16
            unsigned bA = ((jj < 2) ? mwA.x : mwA.y) >> (kb + (jj & 1) * 16);
            unsigned bB = ((jj < 2) ? mwB.x : mwB.y) >> (kb + (jj & 1) * 16);
            float2 aA = make_float2(0.f, 0.f), aB = make_float2(0.f, 0.f);
#pragma unroll
            for (int dp = 0; dp < 16; dp++) {
                float2 v = KV2[cur][kk][dp];
                ffma2(aA, qrA[dp], v);
                ffma2(aB, qrB[dp], v);
            }
            Sb[qA][k0 + kk] = (bA & 1u) ? -1e9f : (aA.x + aA.y);
            Sb[qB][k0 + kk] = (bB & 1u) ? -1e9f : (aB.x + aB.y);
        }
        __syncthreads();
    }

    // ---- issue V chunk 0 now: softmax hides its latency ----
#pragma unroll
    for (int t = 0; t < 4; t++)
        cp_async8(&KV2[0][lkk + t * 16][ldp], Vb + (size_t)(lkk + t * 16) * DM + ldp * 2);
    cp_commit();

    // ---- softmax (4 rows per warp) + fp16 attn write ----
#pragma unroll
    for (int rr = 0; rr < 4; rr++) {
        int q = warp * 4 + rr;
        float mx = -1e30f;
#pragma unroll
        for (int t = 0; t < 4; t++) {
            float4 v = *(float4*)&Sb[q][(lane + t * 32) * 4];
            mx = fmaxf(mx, fmaxf(fmaxf(v.x, v.y), fmaxf(v.z, v.w)));
        }
#pragma unroll
        for (int o = 16; o; o >>= 1) mx = fmaxf(mx, __shfl_xor_sync(0xffffffffu, mx, o));
        float sum = 0.f;
#pragma unroll
        for (int t = 0; t < 4; t++) {
            float4 v = *(float4*)&Sb[q][(lane + t * 32) * 4];
            v.x = __expf(v.x - mx); v.y = __expf(v.y - mx);
            v.z = __expf(v.z - mx); v.w = __expf(v.w - mx);
            *(float4*)&Sb[q][(lane + t * 32) * 4] = v;
            sum += v.x + v.y + v.z + v.w;
        }
#pragma unroll
        for (int o = 16; o; o >>= 1) sum += __shfl_xor_sync(0xffffffffu, sum, o);
        float inv = 1.f / sum;
        long long base = mrow0 + (long long)q * SS;
#pragma unroll
        for (int t = 0; t < 4; t++) {
            float4 v = *(float4*)&Sb[q][(lane + t * 32) * 4];
            v.x *= inv; v.y *= inv; v.z *= inv; v.w *= inv;
            *(float4*)&Sb[q][(lane + t * 32) * 4] = v;
            __half2 h0 = __floats2half2_rn(v.x, v.y);
            __half2 h1 = __floats2half2_rn(v.z, v.w);
            uint2 packed = { *(unsigned*)&h0, *(unsigned*)&h1 };
            *(uint2*)&attn[base + (lane + t * 32) * 4] = packed;   // 8B aligned
        }
    }

    // ---- attn @ V (2 q-rows per thread; V loads shared) ----
    {
        const int r0 = tid >> 4, dp = tid & 15;   // rows r0 and r0+16
        float2 accA = make_float2(0.f, 0.f), accB = make_float2(0.f, 0.f);
        for (int it = 0; it < 8; it++) {
            const int cur = it & 1;
            const int k0 = it * 64;
            if (it < 7) {
                const float* src = Vb + (size_t)(k0 + 64) * DM;
#pragma unroll
                for (int t = 0; t < 4; t++)
                    cp_async8(&KV2[cur ^ 1][lkk + t * 16][ldp], src + (size_t)(lkk + t * 16) * DM + ldp * 2);
                cp_commit();
            }
            if (it < 7) cp_wait<1>(); else cp_wait<0>();
            __syncthreads();   // at it=0 this also publishes softmax's Sb writes
#pragma unroll
            for (int kp = 0; kp < 32; kp++) {
                float2 apA = *(const float2*)&Sb[r0][k0 + 2 * kp];
                float2 apB = *(const float2*)&Sb[r0 + 16][k0 + 2 * kp];
                float2 v0 = KV2[cur][2 * kp][dp];
                float2 v1 = KV2[cur][2 * kp + 1][dp];
                float2 sA0 = {apA.x, apA.x}, sA1 = {apA.y, apA.y};
                float2 sB0 = {apB.x, apB.x}, sB1 = {apB.y, apB.y};
                ffma2(accA, sA0, v0); ffma2(accA, sA1, v1);
                ffma2(accB, sB0, v0); ffma2(accB, sB1, v1);
            }
            __syncthreads();
        }
        *(float2*)&ctx[((size_t)(b * SS + q0 + r0)) * CTXW + h * DKV + dp * 2] = accA;
        *(float2*)&ctx[((size_t)(b * SS + q0 + r0 + 16)) * CTXW + h * DKV + dp * 2] = accB;
    }
}

// ============================================================
// context2 = matrix @ vp2 -> ctx cols [256, 288).
// ============================================================
__global__ __launch_bounds__(256) void ctx2_kernel(
    const float* __restrict__ matrix, const float* __restrict__ vp2, float* __restrict__ ctx)
{
    __shared__ __align__(16) float  Ms[32][68];
    __shared__ __align__(16) float2 Vs[64][17];
    const int b = blockIdx.y, i0 = blockIdx.x * 32;
    const int tid = threadIdx.x;
    const int r = tid >> 3, cq = tid & 7;

    float2 acc0 = make_float2(0.f, 0.f), acc1 = make_float2(0.f, 0.f);
    for (int k0 = 0; k0 < SS; k0 += 64) {
#pragma unroll
        for (int t = 0; t < 2; t++) {
            int idx = tid + t * 256;
            int row = idx >> 4, c4 = idx & 15;
            *(float4*)&Ms[row][c4 * 4] =
                *(const float4*)&matrix[((size_t)(b * SS + i0 + row)) * SS + k0 + c4 * 4];
        }
#pragma unroll
        for (int t = 0; t < 4; t++) {
            int idx = tid + t * 256, kk = idx >> 4, dp = idx & 15;
            Vs[kk][dp] = *(const float2*)&vp2[((size_t)(b * SS + k0 + kk)) * DKV + dp * 2];
        }
        __syncthreads();
#pragma unroll
        for (int kk = 0; kk < 64; kk++) {
            float a = Ms[r][kk];
            float2 a2 = {a, a};
            ffma2(acc0, a2, Vs[kk][cq * 2]);
            ffma2(acc1, a2, Vs[kk][cq * 2 + 1]);
        }
        __syncthreads();
    }
    float4 o4 = {acc0.x, acc0.y, acc1.x, acc1.y};
    *(float4*)&ctx[((size_t)(b * SS + i0 + r)) * CTXW + HH * DKV + cq * 4] = o4;
}

// ============================================================
// Gate v3: attn read as fp16, MLP-36 batched loads,
// LN -> relu -> sigmoid; matrix_out = matrix * g
// ============================================================
__global__ __launch_bounds__(256) void gate_kernel(
    const __half* __restrict__ attn, const float* __restrict__ matrix, float* __restrict__ mout,
    const float* __restrict__ fu_ln_g, const float* __restrict__ fu_ln_b,
    const float* __restrict__ fu_w1, const float* __restrict__ fu_b1,
    const float* __restrict__ fu_w2, const float* __restrict__ fu_b2)
{
    __shared__ float pl[9][32][33];
    __shared__ float pg[9], pb[9], w1[9][6], b1[6], w2[6], b2s;

    int b = blockIdx.z;
    int i0 = blockIdx.y * 32, j0 = blockIdx.x * 32;
    int tid = threadIdx.x;

    if (tid < 9) { pg[tid] = fu_ln_g[tid]; pb[tid] = fu_ln_b[tid]; }
    if (tid >= 32 && tid < 86) { int t = tid - 32; w1[t / 6][t % 6] = fu_w1[t]; }
    if (tid >= 96 && tid < 102) b1[tid - 96] = fu_b1[tid - 96];
    if (tid >= 128 && tid < 134) w2[tid - 128] = fu_w2[tid - 128];
    if (tid == 160) b2s = fu_b2[0];

    // ---- all loads batched first (1 fp32 plane + 8 fp16 planes x 4 rows) ----
    {
        const int jj0 = tid >> 5, ii = tid & 31;
        const float* msrc = matrix + (size_t)b * SS * SS;
        const __half* asrc[8];
#pragma unroll
        for (int c = 0; c < 8; c++)
            asrc[c] = attn + ((size_t)(b * HH + c)) * SS * SS;

        float  mval[4];
        __half aval[8][4];
#pragma unroll
        for (int t = 0; t < 4; t++)
            mval[t] = msrc[(size_t)(j0 + jj0 + t * 8) * SS + i0 + ii];
#pragma unroll
        for (int c = 0; c < 8; c++)
#pragma unroll
            for (int t = 0; t < 4; t++)
                aval[c][t] = asrc[c][(size_t)(j0 + jj0 + t * 8) * SS + i0 + ii];

#pragma unroll
        for (int t = 0; t < 4; t++)
            pl[0][jj0 + t * 8][ii] = mval[t];
#pragma unroll
        for (int c = 0; c < 8; c++)
#pragma unroll
            for (int t = 0; t < 4; t++)
                pl[c + 1][jj0 + t * 8][ii] = __half2float(aval[c][t]);
    }
    __syncthreads();

#pragma unroll
    for (int r = 0; r < 4; r++) {
        int idx = tid + r * 256;
        int ii = idx >> 5, jj = idx & 31;
        float v[9];
        float m = 0.f;
#pragma unroll
        for (int c = 0; c < 9; c++) { v[c] = pl[c][jj][ii]; m += v[c]; }
        m *= (1.f / 9.f);
        float var = 0.f;
#pragma unroll
        for (int c = 0; c < 9; c++) { float dd = v[c] - m; var += dd * dd; }
        var *= (1.f / 9.f);
        float rinv = rsqrtf(var + EPS);
        float y[9];
#pragma unroll
        for (int c = 0; c < 9; c++) y[c] = pg[c] * (v[c] - m) * rinv + pb[c];
        float z = b2s;
#pragma unroll
        for (int j = 0; j < 6; j++) {
            float t = b1[j];
#pragma unroll
            for (int c = 0; c < 9; c++) t += y[c] * w1[c][j];
            t = fmaxf(t, 0.f);
            z += t * w2[j];
        }
        float g = 1.f / (1.f + __expf(-z));
        long long o = ((long long)b * SS + i0 + ii) * SS + j0 + jj;
        mout[o] = matrix[o] * g;
    }
}

// ============================================================
// Final layernorm over 256 channels: one block per row
// ============================================================
__global__ __launch_bounds__(256) void ln_kernel(
    const float* __restrict__ x, const float* __restrict__ g,
    const float* __restrict__ bt, float* __restrict__ out)
{
    int row = blockIdx.x, tid = threadIdx.x;
    float v = x[(long long)row * DM + tid];

    __shared__ float red[8];
    float s = v;
#pragma unroll
    for (int o = 16; o; o >>= 1) s += __shfl_xor_sync(0xffffffffu, s, o);
    if ((tid & 31) == 0) red[tid >> 5] = s;
    __syncthreads();
    float tot = 0.f;
#pragma unroll
    for (int i = 0; i < 8; i++) tot += red[i];
    float m = tot * (1.f / DM);
    __syncthreads();

    float d = v - m;
    float s2 = d * d;
#pragma unroll
    for (int o = 16; o; o >>= 1) s2 += __shfl_xor_sync(0xffffffffu, s2, o);
    if ((tid & 31) == 0) red[tid >> 5] = s2;
    __syncthreads();
    float vtot = 0.f;
#pragma unroll
    for (int i = 0; i < 8; i++) vtot += red[i];
    float var = vtot * (1.f / DM);

    out[(long long)row * DM + tid] = g[tid] * d * rsqrtf(var + EPS) + bt[tid];
}

// ============================================================
extern "C" void kernel_launch(void* const* d_in, const int* in_sizes, int n_in,
                              void* d_out, int out_size)
{
    const float* inQ    = (const float*)d_in[0];
    const float* inK    = (const float*)d_in[1];
    const float* inV    = (const float*)d_in[2];
    const int*   mask   = (const int*)  d_in[3];
    const float* matrix = (const float*)d_in[4];
    const float* W_Q    = (const float*)d_in[5];
    const float* W_K    = (const float*)d_in[6];
    const float* W_V    = (const float*)d_in[7];
    const float* W_V2   = (const float*)d_in[8];
    const float* W_fc   = (const float*)d_in[9];
    const float* ln_g   = (const float*)d_in[10];
    const float* ln_b   = (const float*)d_in[11];
    const float* fu_ln_g= (const float*)d_in[12];
    const float* fu_ln_b= (const float*)d_in[13];
    const float* fu_w1  = (const float*)d_in[14];
    const float* fu_b1  = (const float*)d_in[15];
    const float* fu_w2  = (const float*)d_in[16];
    const float* fu_b2  = (const float*)d_in[17];

    float* out  = (float*)d_out;                            // [B,S,DM]
    float* mout = (float*)d_out + (long long)BB * SS * DM;  // [B,S,S]

    float *pQ, *pK, *pV, *pvp2, *pctx, *pfc;
    __half* pattn;
    unsigned* pmaskp;
    cudaGetSymbolAddress((void**)&pQ, g_Q);
    cudaGetSymbolAddress((void**)&pK, g_K);
    cudaGetSymbolAddress((void**)&pV, g_V);
    cudaGetSymbolAddress((void**)&pattn, g_attn);
    cudaGetSymbolAddress((void**)&pmaskp, g_maskp);
    cudaGetSymbolAddress((void**)&pvp2, g_vp2);
    cudaGetSymbolAddress((void**)&pctx, g_ctx);
    cudaGetSymbolAddress((void**)&pfc, g_fc);

    cudaFuncSetAttribute(attn6_kernel, cudaFuncAttributeMaxDynamicSharedMemorySize, ATTN_SMEM);

    // ---- fork side stream s1 from the main (capture) stream ----
    cudaEventRecord(g_evFork, 0);
    cudaStreamWaitEvent(g_s1, g_evFork, 0);

    // s1: mask bit-pack first (overlaps QKV GEMM on main), then vp2 -> ctx2
    maskpack_kernel<<<1024, 256, 0, g_s1>>>(mask, pmaskp);
    cudaEventRecord(g_evPack, g_s1);
    sgemm_n32_kernel<<<dim3(1, 64), 256, 0, g_s1>>>(inV, W_V2, pvp2, DM, DM);
    ctx2_kernel<<<dim3(16, BB), 256, 0, g_s1>>>(matrix, pvp2, pctx);
    cudaEventRecord(g_evCtx2, g_s1);

    // main: QKV projections; attn needs the packed mask -> wait evPack
    sgemm2_kernel<<<dim3(4, 64, 3), 256>>>(inQ, inK, inV, W_Q, W_K, W_V,
                                           pQ, pK, pV, DM, DM, DM, DM);
    cudaStreamWaitEvent(0, g_evPack, 0);
    attn6_kernel<<<dim3(SS / 32, HH, BB), 256, ATTN_SMEM>>>(pQ, pK, pV, pmaskp, pattn, pctx);
    cudaEventRecord(g_evAttn, 0);

    // s1: gate needs attn -> wait, then run (parallel with fc+ln on main)
    cudaStreamWaitEvent(g_s1, g_evAttn, 0);
    gate_kernel<<<dim3(SS / 32, SS / 32, BB), 256, 0, g_s1>>>(pattn, matrix, mout,
                                                     fu_ln_g, fu_ln_b, fu_w1, fu_b1, fu_w2, fu_b2);
    cudaEventRecord(g_evGate, g_s1);

    // main: fc needs ctx2 (and attn, already ordered) -> wait, then fc + ln
    cudaStreamWaitEvent(0, g_evCtx2, 0);
    sgemm2_kernel<<<dim3(4, 64, 1), 256>>>(pctx, pctx, pctx, W_fc, W_fc, W_fc,
                                           pfc, pfc, pfc, CTXW, CTXW, DM, DM);
    ln_kernel<<<BB * SS, 256>>>(pfc, ln_g, ln_b, out);

    // join: gate must complete before the graph ends
    cudaStreamWaitEvent(0, g_evGate, 0);
}

// round 16
// speedup vs baseline: 1.1785x; 1.1785x over previous
#include <cuda_runtime.h>
#include <cuda_fp16.h>
#include <math.h>

// Problem constants
#define BB 16
#define SS 512
#define DM 256
#define HH 8
#define DKV 32
#define CTXW 288   // DV*(H+1)
#define EPS 1e-5f

// -------- scratch (device globals; no allocation allowed) --------
__device__ float  g_Q[BB * SS * DM];
__device__ float  g_K[BB * SS * DM];
__device__ float  g_V[BB * SS * DM];
__device__ __half g_attn[(long)BB * HH * SS * SS];   // 67 MB (fp16)
__device__ float  g_vp2[BB * SS * DKV];
__device__ float  g_ctx[BB * SS * CTXW];
__device__ float  g_fc[BB * SS * DM];

// -------- one-time stream/event setup (load-time ctor: every
// kernel_launch call performs IDENTICAL work; no in-call guards) --------
static cudaStream_t g_s1;
static cudaEvent_t  g_evFork, g_evAttn0, g_evAttn1, g_evCtx2, g_evGate;
namespace {
struct StreamInit {
    StreamInit() {
        cudaStreamCreateWithFlags(&g_s1, cudaStreamNonBlocking);
        cudaEventCreateWithFlags(&g_evFork, cudaEventDisableTiming);
        cudaEventCreateWithFlags(&g_evAttn0, cudaEventDisableTiming);
        cudaEventCreateWithFlags(&g_evAttn1, cudaEventDisableTiming);
        cudaEventCreateWithFlags(&g_evCtx2, cudaEventDisableTiming);
        cudaEventCreateWithFlags(&g_evGate, cudaEventDisableTiming);
    }
};
StreamInit g_stream_init_;
}

// ---- packed f32x2 FMA (Blackwell FFMA2; PTX-only, ptxas won't auto-fuse) ----
__device__ __forceinline__ void ffma2(float2 &d, const float2 &a, const float2 &b) {
    unsigned long long &dd = reinterpret_cast<unsigned long long &>(d);
    const unsigned long long &aa = reinterpret_cast<const unsigned long long &>(a);
    const unsigned long long &bb = reinterpret_cast<const unsigned long long &>(b);
    asm("fma.rn.f32x2 %0, %1, %2, %0;" : "+l"(dd) : "l"(aa), "l"(bb));
}

// ---- cp.async helpers (8-byte: keeps conflict-free stride-17 smem layout) ----
__device__ __forceinline__ void cp_async8(void* smem, const void* gmem) {
    unsigned saddr = (unsigned)__cvta_generic_to_shared(smem);
    asm volatile("cp.async.ca.shared.global [%0], [%1], 8;" :: "r"(saddr), "l"(gmem));
}
__device__ __forceinline__ void cp_commit() {
    asm volatile("cp.async.commit_group;" ::: "memory");
}
template<int N>
__device__ __forceinline__ void cp_wait() {
    asm volatile("cp.async.wait_group %0;" :: "n"(N) : "memory");
}

// dynamic smem size for attn5: Sb[32][528] f32 + KV2[2][64][17] float2
#define ATTN_SMEM (32 * 528 * 4 + 2 * 64 * 17 * 8)

// ============================================================
// SGEMM v2 (single-buffered inner loop), z-dispatched over up to
// 3 independent (A,B,C) triples. tile 128x64, BK=16, 256 threads.
// ============================================================
__global__ __launch_bounds__(256) void sgemm2_kernel(
    const float* __restrict__ A0, const float* __restrict__ A1, const float* __restrict__ A2,
    const float* __restrict__ B0, const float* __restrict__ B1, const float* __restrict__ B2,
    float* __restrict__ C0, float* __restrict__ C1, float* __restrict__ C2,
    int K, int lda, int ldb, int ldc)
{
    const int z = blockIdx.z;
    const float* A = (z == 0) ? A0 : (z == 1) ? A1 : A2;
    const float* B = (z == 0) ? B0 : (z == 1) ? B1 : B2;
    float*       C = (z == 0) ? C0 : (z == 1) ? C1 : C2;

    __shared__ __align__(16) float As[16][130];  // [k][m], m contiguous
    __shared__ __align__(16) float Bs[16][68];   // [k][n]
    const int tid = threadIdx.x;
    const int tx = tid & 15, ty = tid >> 4;
    const int m0 = blockIdx.y * 128, n0 = blockIdx.x * 64;

    float2 acc[4][4];
#pragma unroll
    for (int i = 0; i < 4; i++)
#pragma unroll
        for (int j = 0; j < 4; j++) acc[i][j] = make_float2(0.f, 0.f);

    for (int k0 = 0; k0 < K; k0 += 16) {
#pragma unroll
        for (int t = 0; t < 2; t++) {
            int idx = tid + t * 256;
            int row = idx >> 2, kq = idx & 3;
            float4 v = *(const float4*)&A[(size_t)(m0 + row) * lda + k0 + kq * 4];
            As[kq * 4 + 0][row] = v.x; As[kq * 4 + 1][row] = v.y;
            As[kq * 4 + 2][row] = v.z; As[kq * 4 + 3][row] = v.w;
        }
        {
            int kk = tid >> 4, nq = tid & 15;
            *(float4*)&Bs[kk][nq * 4] =
                *(const float4*)&B[(size_t)(k0 + kk) * ldb + n0 + nq * 4];
        }
        __syncthreads();
#pragma unroll
        for (int kk = 0; kk < 16; kk++) {
            float2 a[4];
#pragma unroll
            for (int i = 0; i < 4; i++) a[i] = *(float2*)&As[kk][ty * 8 + 2 * i];
            float2 bA = *(float2*)&Bs[kk][tx * 4];
            float2 bB = *(float2*)&Bs[kk][tx * 4 + 2];
            float2 bj[4] = {{bA.x, bA.x}, {bA.y, bA.y}, {bB.x, bB.x}, {bB.y, bB.y}};
#pragma unroll
            for (int j = 0; j < 4; j++)
#pragma unroll
                for (int i = 0; i < 4; i++) ffma2(acc[i][j], a[i], bj[j]);
        }
        __syncthreads();
    }
#pragma unroll
    for (int i = 0; i < 4; i++) {
        int m = m0 + ty * 8 + 2 * i;
        float4 lo = {acc[i][0].x, acc[i][1].x, acc[i][2].x, acc[i][3].x};
        float4 hi = {acc[i][0].y, acc[i][1].y, acc[i][2].y, acc[i][3].y};
        *(float4*)&C[(size_t)m * ldc + n0 + tx * 4] = lo;
        *(float4*)&C[(size_t)(m + 1) * ldc + n0 + tx * 4] = hi;
    }
}

// ============================================================
// SGEMM narrow: N=32 (vp2 projection). tile 128x32, BK=16.
// ============================================================
__global__ __launch_bounds__(256) void sgemm_n32_kernel(
    const float* __restrict__ A, const float* __restrict__ B, float* __restrict__ C,
    int K, int lda)
{
    __shared__ __align__(16) float As[16][130];
    __shared__ __align__(16) float Bs[16][36];
    const int tid = threadIdx.x;
    const int tx = tid & 7, ty = tid >> 3;
    const int m0 = blockIdx.y * 128;

    float2 acc[2][4];
#pragma unroll
    for (int i = 0; i < 2; i++)
#pragma unroll
        for (int j = 0; j < 4; j++) acc[i][j] = make_float2(0.f, 0.f);

    for (int k0 = 0; k0 < K; k0 += 16) {
#pragma unroll
        for (int t = 0; t < 2; t++) {
            int idx = tid + t * 256;
            int row = idx >> 2, kq = idx & 3;
            float4 v = *(const float4*)&A[(size_t)(m0 + row) * lda + k0 + kq * 4];
            As[kq * 4 + 0][row] = v.x; As[kq * 4 + 1][row] = v.y;
            As[kq * 4 + 2][row] = v.z; As[kq * 4 + 3][row] = v.w;
        }
        if (tid < 128) {
            int kk = tid >> 3, nq = tid & 7;
            *(float4*)&Bs[kk][nq * 4] =
                *(const float4*)&B[(size_t)(k0 + kk) * DKV + nq * 4];
        }
        __syncthreads();
#pragma unroll
        for (int kk = 0; kk < 16; kk++) {
            float2 a0 = *(float2*)&As[kk][ty * 4];
            float2 a1 = *(float2*)&As[kk][ty * 4 + 2];
            float2 bA = *(float2*)&Bs[kk][tx * 4];
            float2 bB = *(float2*)&Bs[kk][tx * 4 + 2];
            float2 bj[4] = {{bA.x, bA.x}, {bA.y, bA.y}, {bB.x, bB.x}, {bB.y, bB.y}};
#pragma unroll
            for (int j = 0; j < 4; j++) { ffma2(acc[0][j], a0, bj[j]); ffma2(acc[1][j], a1, bj[j]); }
        }
        __syncthreads();
    }
#pragma unroll
    for (int i = 0; i < 2; i++) {
        int m = m0 + ty * 4 + 2 * i;
        float4 lo = {acc[i][0].x, acc[i][1].x, acc[i][2].x, acc[i][3].x};
        float4 hi = {acc[i][0].y, acc[i][1].y, acc[i][2].y, acc[i][3].y};
        *(float4*)&C[(size_t)m * DKV + tx * 4] = lo;
        *(float4*)&C[(size_t)(m + 1) * DKV + tx * 4] = hi;
    }
}

// ============================================================
// Fused attention v5 (R10/R11 winner) + bbase batch offset (R13).
// 32-q-row tile, 2 q-rows per thread, cp.async double-buffered K/V,
// fp16 attn store. grid (S/32, H, BB/2), 256 threads.
// ============================================================
__global__ __launch_bounds__(256, 2) void attn5_kernel(
    const float* __restrict__ Q, const float* __restrict__ K, const float* __restrict__ V,
    const int* __restrict__ mask, __half* __restrict__ attn, float* __restrict__ ctx,
    int bbase)
{
    extern __shared__ __align__(16) char smem_raw[];
    float  (*Sb)[528]      = reinterpret_cast<float (*)[528]>(smem_raw);             // [32][528]
    float2 (*KV2)[64][17]  = reinterpret_cast<float2 (*)[64][17]>(smem_raw + 32 * 528 * 4); // [2][64][17]

    const int q0 = blockIdx.x * 32;
    const int h = blockIdx.y;
    const int b = blockIdx.z + bbase;
    const int tid = threadIdx.x;
    const int lane = tid & 31, warp = tid >> 5;

    const float* Qb = &Q[((size_t)(b * SS + q0)) * DM + h * DKV];
    const float* Kb = &K[((size_t)(b * SS)) * DM + h * DKV];
    const float* Vb = &V[((size_t)(b * SS)) * DM + h * DKV];
    const long long mrow0 = (((long long)(b * HH + h)) * SS + q0) * SS;

    const int lkk = tid >> 4, ldp = tid & 15;   // cp.async loader mapping

    // ---- issue K chunk 0 -> buf 0 immediately ----
#pragma unroll
    for (int t = 0; t < 4; t++)
        cp_async8(&KV2[0][lkk + t * 16][ldp], Kb + (size_t)(lkk + t * 16) * DM + ldp * 2);
    cp_commit();

    // ---- stage scaled Q (32x16 float2) into KV2[1], then to registers ----
    {
        int sq = tid >> 3, dq = tid & 7;
#pragma unroll
        for (int t = 0; t < 2; t++) {
            int dp = dq + t * 8;
            float2 v = *(const float2*)&Qb[(size_t)sq * DM + dp * 2];
            v.x *= 0.17677669529663687f; v.y *= 0.17677669529663687f;
            KV2[1][sq][dp] = v;
        }
    }
    __syncthreads();
    const int p  = (warp << 1) | (lane >> 4);   // 0..15 row-pair id
    const int qA = p, qB = p + 16;
    float2 qrA[16], qrB[16];
#pragma unroll
    for (int dp = 0; dp < 16; dp++) { qrA[dp] = KV2[1][qA][dp]; qrB[dp] = KV2[1][qB][dp]; }
    __syncthreads();   // all Q reads done before it=0 prefetch overwrites buf 1

    // ---- scores + mask (2 q-rows per thread) ----
    const int kb = lane & 15;
    const long long mrowA = mrow0 + (long long)qA * SS;
    const long long mrowB = mrow0 + (long long)qB * SS;
    for (int it = 0; it < 8; it++) {
        const int cur = it & 1;
        const int k0 = it * 64;
        if (it < 7) {
            const float* src = Kb + (size_t)(k0 + 64) * DM;
#pragma unroll
            for (int t = 0; t < 4; t++)
                cp_async8(&KV2[cur ^ 1][lkk + t * 16][ldp], src + (size_t)(lkk + t * 16) * DM + ldp * 2);
            cp_commit();
        }
        int mkA[4], mkB[4];
#pragma unroll
        for (int jj = 0; jj < 4; jj++) {
            mkA[jj] = mask[mrowA + k0 + kb + jj * 16];
            mkB[jj] = mask[mrowB + k0 + kb + jj * 16];
        }
        if (it < 7) cp_wait<1>(); else cp_wait<0>();
        __syncthreads();
#pragma unroll
        for (int jj = 0; jj < 4; jj++) {
            int kk = kb + jj * 16;
            float2 aA = make_float2(0.f, 0.f), aB = make_float2(0.f, 0.f);
#pragma unroll
            for (int dp = 0; dp < 16; dp++) {
                float2 v = KV2[cur][kk][dp];
                ffma2(aA, qrA[dp], v);
                ffma2(aB, qrB[dp], v);
            }
            Sb[qA][k0 + kk] = mkA[jj] ? -1e9f : (aA.x + aA.y);
            Sb[qB][k0 + kk] = mkB[jj] ? -1e9f : (aB.x + aB.y);
        }
        __syncthreads();
    }

    // ---- issue V chunk 0 now: softmax hides its latency ----
#pragma unroll
    for (int t = 0; t < 4; t++)
        cp_async8(&KV2[0][lkk + t * 16][ldp], Vb + (size_t)(lkk + t * 16) * DM + ldp * 2);
    cp_commit();

    // ---- softmax (4 rows per warp) + fp16 attn write ----
#pragma unroll
    for (int rr = 0; rr < 4; rr++) {
        int q = warp * 4 + rr;
        float mx = -1e30f;
#pragma unroll
        for (int t = 0; t < 4; t++) {
            float4 v = *(float4*)&Sb[q][(lane + t * 32) * 4];
            mx = fmaxf(mx, fmaxf(fmaxf(v.x, v.y), fmaxf(v.z, v.w)));
        }
#pragma unroll
        for (int o = 16; o; o >>= 1) mx = fmaxf(mx, __shfl_xor_sync(0xffffffffu, mx, o));
        float sum = 0.f;
#pragma unroll
        for (int t = 0; t < 4; t++) {
            float4 v = *(float4*)&Sb[q][(lane + t * 32) * 4];
            v.x = __expf(v.x - mx); v.y = __expf(v.y - mx);
            v.z = __expf(v.z - mx); v.w = __expf(v.w - mx);
            *(float4*)&Sb[q][(lane + t * 32) * 4] = v;
            sum += v.x + v.y + v.z + v.w;
        }
#pragma unroll
        for (int o = 16; o; o >>= 1) sum += __shfl_xor_sync(0xffffffffu, sum, o);
        float inv = 1.f / sum;
        long long base = mrow0 + (long long)q * SS;
#pragma unroll
        for (int t = 0; t < 4; t++) {
            float4 v = *(float4*)&Sb[q][(lane + t * 32) * 4];
            v.x *= inv; v.y *= inv; v.z *= inv; v.w *= inv;
            *(float4*)&Sb[q][(lane + t * 32) * 4] = v;
            __half2 h0 = __floats2half2_rn(v.x, v.y);
            __half2 h1 = __floats2half2_rn(v.z, v.w);
            uint2 packed = { *(unsigned*)&h0, *(unsigned*)&h1 };
            *(uint2*)&attn[base + (lane + t * 32) * 4] = packed;   // 8B aligned
        }
    }

    // ---- attn @ V (2 q-rows per thread; V loads shared) ----
    {
        const int r0 = tid >> 4, dp = tid & 15;   // rows r0 and r0+16
        float2 accA = make_float2(0.f, 0.f), accB = make_float2(0.f, 0.f);
        for (int it = 0; it < 8; it++) {
            const int cur = it & 1;
            const int k0 = it * 64;
            if (it < 7) {
                const float* src = Vb + (size_t)(k0 + 64) * DM;
#pragma unroll
                for (int t = 0; t < 4; t++)
                    cp_async8(&KV2[cur ^ 1][lkk + t * 16][ldp], src + (size_t)(lkk + t * 16) * DM + ldp * 2);
                cp_commit();
            }
            if (it < 7) cp_wait<1>(); else cp_wait<0>();
            __syncthreads();   // at it=0 this also publishes softmax's Sb writes
#pragma unroll
            for (int kp = 0; kp < 32; kp++) {
                float2 apA = *(const float2*)&Sb[r0][k0 + 2 * kp];
                float2 apB = *(const float2*)&Sb[r0 + 16][k0 + 2 * kp];
                float2 v0 = KV2[cur][2 * kp][dp];
                float2 v1 = KV2[cur][2 * kp + 1][dp];
                float2 sA0 = {apA.x, apA.x}, sA1 = {apA.y, apA.y};
                float2 sB0 = {apB.x, apB.x}, sB1 = {apB.y, apB.y};
                ffma2(accA, sA0, v0); ffma2(accA, sA1, v1);
                ffma2(accB, sB0, v0); ffma2(accB, sB1, v1);
            }
            __syncthreads();
        }
        *(float2*)&ctx[((size_t)(b * SS + q0 + r0)) * CTXW + h * DKV + dp * 2] = accA;
        *(float2*)&ctx[((size_t)(b * SS + q0 + r0 + 16)) * CTXW + h * DKV + dp * 2] = accB;
    }
}

// ============================================================
// context2 = matrix @ vp2 -> ctx cols [256, 288).
// ============================================================
__global__ __launch_bounds__(256) void ctx2_kernel(
    const float* __restrict__ matrix, const float* __restrict__ vp2, float* __restrict__ ctx)
{
    __shared__ __align__(16) float  Ms[32][68];
    __shared__ __align__(16) float2 Vs[64][17];
    const int b = blockIdx.y, i0 = blockIdx.x * 32;
    const int tid = threadIdx.x;
    const int r = tid >> 3, cq = tid & 7;

    float2 acc0 = make_float2(0.f, 0.f), acc1 = make_float2(0.f, 0.f);
    for (int k0 = 0; k0 < SS; k0 += 64) {
#pragma unroll
        for (int t = 0; t < 2; t++) {
            int idx = tid + t * 256;
            int row = idx >> 4, c4 = idx & 15;
            *(float4*)&Ms[row][c4 * 4] =
                *(const float4*)&matrix[((size_t)(b * SS + i0 + row)) * SS + k0 + c4 * 4];
        }
#pragma unroll
        for (int t = 0; t < 4; t++) {
            int idx = tid + t * 256, kk = idx >> 4, dp = idx & 15;
            Vs[kk][dp] = *(const float2*)&vp2[((size_t)(b * SS + k0 + kk)) * DKV + dp * 2];
        }
        __syncthreads();
#pragma unroll
        for (int kk = 0; kk < 64; kk++) {
            float a = Ms[r][kk];
            float2 a2 = {a, a};
            ffma2(acc0, a2, Vs[kk][cq * 2]);
            ffma2(acc1, a2, Vs[kk][cq * 2 + 1]);
        }
        __syncthreads();
    }
    float4 o4 = {acc0.x, acc0.y, acc1.x, acc1.y};
    *(float4*)&ctx[((size_t)(b * SS + i0 + r)) * CTXW + HH * DKV + cq * 4] = o4;
}

// ============================================================
// Gate v3 + bbase batch offset (R13): attn read as fp16, MLP-36
// batched loads, LN -> relu -> sigmoid; matrix_out = matrix * g
// ============================================================
__global__ __launch_bounds__(256) void gate_kernel(
    const __half* __restrict__ attn, const float* __restrict__ matrix, float* __restrict__ mout,
    const float* __restrict__ fu_ln_g, const float* __restrict__ fu_ln_b,
    const float* __restrict__ fu_w1, const float* __restrict__ fu_b1,
    const float* __restrict__ fu_w2, const float* __restrict__ fu_b2,
    int bbase)
{
    __shared__ float pl[9][32][33];
    __shared__ float pg[9], pb[9], w1[9][6], b1[6], w2[6], b2s;

    int b = blockIdx.z + bbase;
    int i0 = blockIdx.y * 32, j0 = blockIdx.x * 32;
    int tid = threadIdx.x;

    if (tid < 9) { pg[tid] = fu_ln_g[tid]; pb[tid] = fu_ln_b[tid]; }
    if (tid >= 32 && tid < 86) { int t = tid - 32; w1[t / 6][t % 6] = fu_w1[t]; }
    if (tid >= 96 && tid < 102) b1[tid - 96] = fu_b1[tid - 96];
    if (tid >= 128 && tid < 134) w2[tid - 128] = fu_w2[tid - 128];
    if (tid == 160) b2s = fu_b2[0];

    // ---- all loads batched first (1 fp32 plane + 8 fp16 planes x 4 rows) ----
    {
        const int jj0 = tid >> 5, ii = tid & 31;
        const float* msrc = matrix + (size_t)b * SS * SS;
        const __half* asrc[8];
#pragma unroll
        for (int c = 0; c < 8; c++)
            asrc[c] = attn + ((size_t)(b * HH + c)) * SS * SS;

        float  mval[4];
        __half aval[8][4];
#pragma unroll
        for (int t = 0; t < 4; t++)
            mval[t] = msrc[(size_t)(j0 + jj0 + t * 8) * SS + i0 + ii];
#pragma unroll
        for (int c = 0; c < 8; c++)
#pragma unroll
            for (int t = 0; t < 4; t++)
                aval[c][t] = asrc[c][(size_t)(j0 + jj0 + t * 8) * SS + i0 + ii];

#pragma unroll
        for (int t = 0; t < 4; t++)
            pl[0][jj0 + t * 8][ii] = mval[t];
#pragma unroll
        for (int c = 0; c < 8; c++)
#pragma unroll
            for (int t = 0; t < 4; t++)
                pl[c + 1][jj0 + t * 8][ii] = __half2float(aval[c][t]);
    }
    __syncthreads();

#pragma unroll
    for (int r = 0; r < 4; r++) {
        int idx = tid + r * 256;
        int ii = idx >> 5, jj = idx & 31;
        float v[9];
        float m = 0.f;
#pragma unroll
        for (int c = 0; c < 9; c++) { v[c] = pl[c][jj][ii]; m += v[c]; }
        m *= (1.f / 9.f);
        float var = 0.f;
#pragma unroll
        for (int c = 0; c < 9; c++) { float dd = v[c] - m; var += dd * dd; }
        var *= (1.f / 9.f);
        float rinv = rsqrtf(var + EPS);
        float y[9];
#pragma unroll
        for (int c = 0; c < 9; c++) y[c] = pg[c] * (v[c] - m) * rinv + pb[c];
        float z = b2s;
#pragma unroll
        for (int j = 0; j < 6; j++) {
            float t = b1[j];
#pragma unroll
            for (int c = 0; c < 9; c++) t += y[c] * w1[c][j];
            t = fmaxf(t, 0.f);
            z += t * w2[j];
        }
        float g = 1.f / (1.f + __expf(-z));
        long long o = ((long long)b * SS + i0 + ii) * SS + j0 + jj;
        mout[o] = matrix[o] * g;
    }
}

// ============================================================
// Final layernorm over 256 channels: one block per row
// ============================================================
__global__ __launch_bounds__(256) void ln_kernel(
    const float* __restrict__ x, const float* __restrict__ g,
    const float* __restrict__ bt, float* __restrict__ out)
{
    int row = blockIdx.x, tid = threadIdx.x;
    float v = x[(long long)row * DM + tid];

    __shared__ float red[8];
    float s = v;
#pragma unroll
    for (int o = 16; o; o >>= 1) s += __shfl_xor_sync(0xffffffffu, s, o);
    if ((tid & 31) == 0) red[tid >> 5] = s;
    __syncthreads();
    float tot = 0.f;
#pragma unroll
    for (int i = 0; i < 8; i++) tot += red[i];
    float m = tot * (1.f / DM);
    __syncthreads();

    float d = v - m;
    float s2 = d * d;
#pragma unroll
    for (int o = 16; o; o >>= 1) s2 += __shfl_xor_sync(0xffffffffu, s2, o);
    if ((tid & 31) == 0) red[tid >> 5] = s2;
    __syncthreads();
    float vtot = 0.f;
#pragma unroll
    for (int i = 0; i < 8; i++) vtot += red[i];
    float var = vtot * (1.f / DM);

    out[(long long)row * DM + tid] = g[tid] * d * rsqrtf(var + EPS) + bt[tid];
}

// ============================================================
extern "C" void kernel_launch(void* const* d_in, const int* in_sizes, int n_in,
                              void* d_out, int out_size)
{
    const float* inQ    = (const float*)d_in[0];
    const float* inK    = (const float*)d_in[1];
    const float* inV    = (const float*)d_in[2];
    const int*   mask   = (const int*)  d_in[3];
    const float* matrix = (const float*)d_in[4];
    const float* W_Q    = (const float*)d_in[5];
    const float* W_K    = (const float*)d_in[6];
    const float* W_V    = (const float*)d_in[7];
    const float* W_V2   = (const float*)d_in[8];
    const float* W_fc   = (const float*)d_in[9];
    const float* ln_g   = (const float*)d_in[10];
    const float* ln_b   = (const float*)d_in[11];
    const float* fu_ln_g= (const float*)d_in[12];
    const float* fu_ln_b= (const float*)d_in[13];
    const float* fu_w1  = (const float*)d_in[14];
    const float* fu_b1  = (const float*)d_in[15];
    const float* fu_w2  = (const float*)d_in[16];
    const float* fu_b2  = (const float*)d_in[17];

    float* out  = (float*)d_out;                            // [B,S,DM]
    float* mout = (float*)d_out + (long long)BB * SS * DM;  // [B,S,S]

    float *pQ, *pK, *pV, *pvp2, *pctx, *pfc;
    __half* pattn;
    cudaGetSymbolAddress((void**)&pQ, g_Q);
    cudaGetSymbolAddress((void**)&pK, g_K);
    cudaGetSymbolAddress((void**)&pV, g_V);
    cudaGetSymbolAddress((void**)&pattn, g_attn);
    cudaGetSymbolAddress((void**)&pvp2, g_vp2);
    cudaGetSymbolAddress((void**)&pctx, g_ctx);
    cudaGetSymbolAddress((void**)&pfc, g_fc);

    cudaFuncSetAttribute(attn5_kernel, cudaFuncAttributeMaxDynamicSharedMemorySize, ATTN_SMEM);

    // ---- fork side stream s1 from the main (capture) stream ----
    cudaEventRecord(g_evFork, 0);
    cudaStreamWaitEvent(g_s1, g_evFork, 0);

    // s1 (parallel with QKV+attn on main): vp2 -> ctx2
    sgemm_n32_kernel<<<dim3(1, 64), 256, 0, g_s1>>>(inV, W_V2, pvp2, DM, DM);
    ctx2_kernel<<<dim3(16, BB), 256, 0, g_s1>>>(matrix, pvp2, pctx);
    cudaEventRecord(g_evCtx2, g_s1);

    // main: QKV projections, then attention in TWO batch halves
    sgemm2_kernel<<<dim3(4, 64, 3), 256>>>(inQ, inK, inV, W_Q, W_K, W_V,
                                           pQ, pK, pV, DM, DM, DM, DM);
    attn5_kernel<<<dim3(SS / 32, HH, BB / 2), 256, ATTN_SMEM>>>(pQ, pK, pV, mask, pattn, pctx, 0);
    cudaEventRecord(g_evAttn0, 0);
    attn5_kernel<<<dim3(SS / 32, HH, BB / 2), 256, ATTN_SMEM>>>(pQ, pK, pV, mask, pattn, pctx, BB / 2);
    cudaEventRecord(g_evAttn1, 0);

    // s1: gate half 0 overlaps attention half 1; gate half 1 overlaps fc+ln
    cudaStreamWaitEvent(g_s1, g_evAttn0, 0);
    gate_kernel<<<dim3(SS / 32, SS / 32, BB / 2), 256, 0, g_s1>>>(pattn, matrix, mout,
                                                     fu_ln_g, fu_ln_b, fu_w1, fu_b1, fu_w2, fu_b2, 0);
    cudaStreamWaitEvent(g_s1, g_evAttn1, 0);
    gate_kernel<<<dim3(SS / 32, SS / 32, BB / 2), 256, 0, g_s1>>>(pattn, matrix, mout,
                                                     fu_ln_g, fu_ln_b, fu_w1, fu_b1, fu_w2, fu_b2, BB / 2);
    cudaEventRecord(g_evGate, g_s1);

    // main: fc needs ctx2 (attn already ordered on main) -> wait, then fc + ln
    cudaStreamWaitEvent(0, g_evCtx2, 0);
    sgemm2_kernel<<<dim3(4, 64, 1), 256>>>(pctx, pctx, pctx, W_fc, W_fc, W_fc,
                                           pfc, pfc, pfc, CTXW, CTXW, DM, DM);
    ln_kernel<<<BB * SS, 256>>>(pfc, ln_g, ln_b, out);

    // join: gate must complete before the graph ends
    cudaStreamWaitEvent(0, g_evGate, 0);
}